// round 1
// baseline (speedup 1.0000x reference)
#include <cuda_runtime.h>

#define NV 128
#define NITER 16

// One warp per batch element. A (128x128 fp32, 64KB) lives in SMEM for all 16
// iterations, stored column-major with an XOR chunk swizzle so both the
// transposed store (load phase) and per-column LDS.128 reads (solve phase)
// are bank-conflict-free.
//
// Lane l owns rows 4l..4l+3. Per iteration:
//   forward substitution M dx = F with M = diag(A_ii + 3 x_i^2) + omega*strict_lower(A)
//   processed in 32 groups of 4 columns; each group's dx is produced by the
//   owning lane via a local 4x4 trisolve and broadcast with shfl. All lanes
//   accumulate s += A[:,c]*dx_c over ALL columns, so after the loop s = A@dx,
//   giving the incremental residual update
//   F <- F - omega*(A@dx) - x^3 + x_new^3  (exactly A@x_new + x_new^3 - b).
__global__ void __launch_bounds__(32, 3)
newton_sor_kernel(const float* __restrict__ Xin,
                  const float* __restrict__ A,
                  const float* __restrict__ Bv,
                  const float* __restrict__ Om,
                  float* __restrict__ Xout)
{
    extern __shared__ float As[];          // swizzled column-major [128][128]
    const int batch = blockIdx.x;
    const int lane  = threadIdx.x;         // 0..31
    const float* Ab = A + (size_t)batch * (NV * NV);

    // diagonal + intra-group strict-lower entries for rows 4l..4l+3
    float d0=0.f,d1=0.f,d2=0.f,d3=0.f;
    float a10=0.f,a20=0.f,a21=0.f,a30=0.f,a31=0.f,a32=0.f;

    // ---- Load A: coalesced LDG.128, 4x4 register transpose, swizzled STS.128
#pragma unroll
    for (int ib = 0; ib < 32; ++ib) {
        const float4 r0 = *(const float4*)(Ab + (size_t)(4*ib+0)*NV + 4*lane);
        const float4 r1 = *(const float4*)(Ab + (size_t)(4*ib+1)*NV + 4*lane);
        const float4 r2 = *(const float4*)(Ab + (size_t)(4*ib+2)*NV + 4*lane);
        const float4 r3 = *(const float4*)(Ab + (size_t)(4*ib+3)*NV + 4*lane);
        if (lane == ib) {                  // this lane's diagonal 4x4 block
            d0 = r0.x; d1 = r1.y; d2 = r2.z; d3 = r3.w;
            a10 = r1.x;
            a20 = r2.x; a21 = r2.y;
            a30 = r3.x; a31 = r3.y; a32 = r3.z;
        }
        // column j = 4*lane+k holds rows 4*ib..4*ib+3 contiguously
        float* base = As + (4*lane)*NV + 4*(ib ^ (lane & 7));
        *(float4*)(base + 0*NV) = make_float4(r0.x, r1.x, r2.x, r3.x);
        *(float4*)(base + 1*NV) = make_float4(r0.y, r1.y, r2.y, r3.y);
        *(float4*)(base + 2*NV) = make_float4(r0.z, r1.z, r2.z, r3.z);
        *(float4*)(base + 3*NV) = make_float4(r0.w, r1.w, r2.w, r3.w);
    }
    __syncwarp();

    float4 xv = *(const float4*)(Xin + (size_t)batch*NV + 4*lane);
    const float4 bv = *(const float4*)(Bv + (size_t)batch*NV + 4*lane);
    const float om = Om[batch];

    // ---- Initial residual F = A@x + x^3 - b
    float s0 = 0.f, s1 = 0.f, s2 = 0.f, s3 = 0.f;
#pragma unroll
    for (int g = 0; g < 32; ++g) {
        const float e0 = __shfl_sync(0xffffffffu, xv.x, g);
        const float e1 = __shfl_sync(0xffffffffu, xv.y, g);
        const float e2 = __shfl_sync(0xffffffffu, xv.z, g);
        const float e3 = __shfl_sync(0xffffffffu, xv.w, g);
        const float* cb = As + (4*g)*NV + 4*(lane ^ (g & 7));
        const float4 A0 = *(const float4*)(cb + 0*NV);
        const float4 A1 = *(const float4*)(cb + 1*NV);
        const float4 A2 = *(const float4*)(cb + 2*NV);
        const float4 A3 = *(const float4*)(cb + 3*NV);
        s0 = fmaf(A0.x,e0, fmaf(A1.x,e1, fmaf(A2.x,e2, fmaf(A3.x,e3, s0))));
        s1 = fmaf(A0.y,e0, fmaf(A1.y,e1, fmaf(A2.y,e2, fmaf(A3.y,e3, s1))));
        s2 = fmaf(A0.z,e0, fmaf(A1.z,e1, fmaf(A2.z,e2, fmaf(A3.z,e3, s2))));
        s3 = fmaf(A0.w,e0, fmaf(A1.w,e1, fmaf(A2.w,e2, fmaf(A3.w,e3, s3))));
    }
    float F0 = s0 + xv.x*xv.x*xv.x - bv.x;
    float F1 = s1 + xv.y*xv.y*xv.y - bv.y;
    float F2 = s2 + xv.z*xv.z*xv.z - bv.z;
    float F3 = s3 + xv.w*xv.w*xv.w - bv.w;

    // ---- Newton-SOR iterations (fixed count; see analysis)
#pragma unroll 1
    for (int it = 0; it < NITER; ++it) {
        const float w0 = 1.0f / fmaf(3.0f*xv.x, xv.x, d0);
        const float w1 = 1.0f / fmaf(3.0f*xv.y, xv.y, d1);
        const float w2 = 1.0f / fmaf(3.0f*xv.z, xv.z, d2);
        const float w3 = 1.0f / fmaf(3.0f*xv.w, xv.w, d3);

        s0 = s1 = s2 = s3 = 0.f;
        float m0 = 0.f, m1 = 0.f, m2 = 0.f, m3 = 0.f;   // this lane's dx

#pragma unroll
        for (int g = 0; g < 32; ++g) {
            // local 4x4 candidate trisolve (valid for lane g; SIMT-uniform)
            const float dx0 = fmaf(-om, s0, F0) * w0;
            const float u1  = fmaf(a10, dx0, s1);
            const float dx1 = fmaf(-om, u1, F1) * w1;
            const float u2  = fmaf(a21, dx1, fmaf(a20, dx0, s2));
            const float dx2 = fmaf(-om, u2, F2) * w2;
            const float u3  = fmaf(a32, dx2, fmaf(a31, dx1, fmaf(a30, dx0, s3)));
            const float dx3 = fmaf(-om, u3, F3) * w3;

            const float e0 = __shfl_sync(0xffffffffu, dx0, g);
            const float e1 = __shfl_sync(0xffffffffu, dx1, g);
            const float e2 = __shfl_sync(0xffffffffu, dx2, g);
            const float e3 = __shfl_sync(0xffffffffu, dx3, g);
            if (lane == g) { m0 = dx0; m1 = dx1; m2 = dx2; m3 = dx3; }

            // apply columns 4g..4g+3 to all rows (builds full A@dx)
            const float* cb = As + (4*g)*NV + 4*(lane ^ (g & 7));
            const float4 A0 = *(const float4*)(cb + 0*NV);
            const float4 A1 = *(const float4*)(cb + 1*NV);
            const float4 A2 = *(const float4*)(cb + 2*NV);
            const float4 A3 = *(const float4*)(cb + 3*NV);
            s0 = fmaf(A0.x,e0, fmaf(A1.x,e1, fmaf(A2.x,e2, fmaf(A3.x,e3, s0))));
            s1 = fmaf(A0.y,e0, fmaf(A1.y,e1, fmaf(A2.y,e2, fmaf(A3.y,e3, s1))));
            s2 = fmaf(A0.z,e0, fmaf(A1.z,e1, fmaf(A2.z,e2, fmaf(A3.z,e3, s2))));
            s3 = fmaf(A0.w,e0, fmaf(A1.w,e1, fmaf(A2.w,e2, fmaf(A3.w,e3, s3))));
        }

        // x <- x - omega*dx ;  F <- F - omega*(A@dx) - x^3 + x_new^3
        const float xn0 = fmaf(-om, m0, xv.x);
        const float xn1 = fmaf(-om, m1, xv.y);
        const float xn2 = fmaf(-om, m2, xv.z);
        const float xn3 = fmaf(-om, m3, xv.w);
        F0 = fmaf(-om, s0, F0) - xv.x*xv.x*xv.x + xn0*xn0*xn0;
        F1 = fmaf(-om, s1, F1) - xv.y*xv.y*xv.y + xn1*xn1*xn1;
        F2 = fmaf(-om, s2, F2) - xv.z*xv.z*xv.z + xn2*xn2*xn2;
        F3 = fmaf(-om, s3, F3) - xv.w*xv.w*xv.w + xn3*xn3*xn3;
        xv.x = xn0; xv.y = xn1; xv.z = xn2; xv.w = xn3;
    }

    *(float4*)(Xout + (size_t)batch*NV + 4*lane) = xv;
}

extern "C" void kernel_launch(void* const* d_in, const int* in_sizes, int n_in,
                              void* d_out, int out_size)
{
    const float* x  = (const float*)d_in[0];   // (B,128)
    const float* A  = (const float*)d_in[1];   // (B,128,128)
    const float* b  = (const float*)d_in[2];   // (B,128)
    const float* om = (const float*)d_in[3];   // (B,1)

    const int B = in_sizes[1] / (NV * NV);
    const int smem = NV * NV * (int)sizeof(float);   // 64 KB

    cudaFuncSetAttribute(newton_sor_kernel,
                         cudaFuncAttributeMaxDynamicSharedMemorySize, smem);
    newton_sor_kernel<<<B, 32, smem>>>(x, A, b, om, (float*)d_out);
}

// round 3
// speedup vs baseline: 3.5150x; 3.5150x over previous
#include <cuda_runtime.h>

#define NV 128
#define NITER 16

// One warp per batch element. A (128x128 fp32, 64KB) lives in SMEM for all 16
// iterations, stored column-major with an XOR chunk swizzle (conflict-free for
// both the transposed store and the per-column LDS.128 reads).
//
// Lane l owns rows 4l..4l+3. Forward substitution for
//   M dx = F,  M = diag(A_ii + 3 x_i^2) + omega * strict_lower(A)
// runs in 32 groups of 4 rows. The 4x4 within-group solve uses the exact
// expansion (I+N)^-1 = I - N + N^2 - N^3 (N strictly lower, nilpotent), built
// once per iteration OFF the critical path, so on-path dx cost is a short
// FMA tree and dx0/shfl issue almost immediately.
// Every lane accumulates s += A[:,c]*dx_c over ALL 128 columns, yielding the
// full A@dx for the incremental residual update
//   F <- F - omega*(A@dx) - x^3 + x_new^3.
__global__ void __launch_bounds__(32, 3)
newton_sor_kernel(const float* __restrict__ Xin,
                  const float* __restrict__ A,
                  const float* __restrict__ Bv,
                  const float* __restrict__ Om,
                  float* __restrict__ Xout)
{
    extern __shared__ float As[];          // swizzled column-major [128][128]
    const int batch = blockIdx.x;
    const int lane  = threadIdx.x;         // 0..31
    const float* Ab = A + (size_t)batch * (NV * NV);

    // diagonal + intra-group strict-lower entries for rows 4l..4l+3
    float d0=0.f,d1=0.f,d2=0.f,d3=0.f;
    float a10=0.f,a20=0.f,a21=0.f,a30=0.f,a31=0.f,a32=0.f;

    // ---- Load A: coalesced LDG.128, 4x4 register transpose, swizzled STS.128
#pragma unroll 4
    for (int ib = 0; ib < 32; ++ib) {
        const float4 r0 = *(const float4*)(Ab + (size_t)(4*ib+0)*NV + 4*lane);
        const float4 r1 = *(const float4*)(Ab + (size_t)(4*ib+1)*NV + 4*lane);
        const float4 r2 = *(const float4*)(Ab + (size_t)(4*ib+2)*NV + 4*lane);
        const float4 r3 = *(const float4*)(Ab + (size_t)(4*ib+3)*NV + 4*lane);
        if (lane == ib) {                  // this lane's diagonal 4x4 block
            d0 = r0.x; d1 = r1.y; d2 = r2.z; d3 = r3.w;
            a10 = r1.x;
            a20 = r2.x; a21 = r2.y;
            a30 = r3.x; a31 = r3.y; a32 = r3.z;
        }
        float* base = As + (4*lane)*NV + 4*(ib ^ (lane & 7));
        *(float4*)(base + 0*NV) = make_float4(r0.x, r1.x, r2.x, r3.x);
        *(float4*)(base + 1*NV) = make_float4(r0.y, r1.y, r2.y, r3.y);
        *(float4*)(base + 2*NV) = make_float4(r0.z, r1.z, r2.z, r3.z);
        *(float4*)(base + 3*NV) = make_float4(r0.w, r1.w, r2.w, r3.w);
    }
    __syncwarp();

    float4 xv = *(const float4*)(Xin + (size_t)batch*NV + 4*lane);
    const float4 bv = *(const float4*)(Bv + (size_t)batch*NV + 4*lane);
    const float om = Om[batch];

    // ---- Initial residual F = A@x + x^3 - b (throughput pass; e's known upfront)
    float s0 = 0.f, s1 = 0.f, s2 = 0.f, s3 = 0.f;
#pragma unroll 4
    for (int g = 0; g < 32; ++g) {
        const float e0 = __shfl_sync(0xffffffffu, xv.x, g);
        const float e1 = __shfl_sync(0xffffffffu, xv.y, g);
        const float e2 = __shfl_sync(0xffffffffu, xv.z, g);
        const float e3 = __shfl_sync(0xffffffffu, xv.w, g);
        const float* cb = As + (4*g)*NV + 4*(lane ^ (g & 7));
        const float4 A0 = *(const float4*)(cb + 0*NV);
        const float4 A1 = *(const float4*)(cb + 1*NV);
        const float4 A2 = *(const float4*)(cb + 2*NV);
        const float4 A3 = *(const float4*)(cb + 3*NV);
        s0 = fmaf(A3.x,e3, fmaf(A2.x,e2, fmaf(A1.x,e1, fmaf(A0.x,e0, s0))));
        s1 = fmaf(A3.y,e3, fmaf(A2.y,e2, fmaf(A1.y,e1, fmaf(A0.y,e0, s1))));
        s2 = fmaf(A3.z,e3, fmaf(A2.z,e2, fmaf(A1.z,e1, fmaf(A0.z,e0, s2))));
        s3 = fmaf(A3.w,e3, fmaf(A2.w,e2, fmaf(A1.w,e1, fmaf(A0.w,e0, s3))));
    }
    float F0 = s0 + xv.x*xv.x*xv.x - bv.x;
    float F1 = s1 + xv.y*xv.y*xv.y - bv.y;
    float F2 = s2 + xv.z*xv.z*xv.z - bv.z;
    float F3 = s3 + xv.w*xv.w*xv.w - bv.w;

    // ---- Newton-SOR iterations (fixed count; global-norm early exit would
    //      only add iterations past convergence, which cannot move x by >tol)
#pragma unroll 1
    for (int it = 0; it < NITER; ++it) {
        // Per-iteration solve coefficients (OFF the critical path).
        const float w0 = __fdividef(1.0f, fmaf(3.0f*xv.x, xv.x, d0));
        const float w1 = __fdividef(1.0f, fmaf(3.0f*xv.y, xv.y, d1));
        const float w2 = __fdividef(1.0f, fmaf(3.0f*xv.z, xv.z, d2));
        const float w3 = __fdividef(1.0f, fmaf(3.0f*xv.w, xv.w, d3));
        // N = om*W*L (strictly lower); (I+N)^{-1} = I - N + N^2 - N^3 (exact)
        const float n10 = om*w1*a10;
        const float n20 = om*w2*a20, n21 = om*w2*a21;
        const float n30 = om*w3*a30, n31 = om*w3*a31, n32 = om*w3*a32;
        const float c20 = fmaf(n21, n10, -n20);
        const float c31 = fmaf(n32, n21, -n31);
        const float t30 = fmaf(-n32, n21, n31);
        const float c30 = fmaf(t30, n10, fmaf(n32, n20, -n30));
        // dx = Bm * (F - om*s), Bm lower-tri with diag = w
        const float B10 = -n10*w0;
        const float B20 =  c20*w0, B21 = -n21*w1;
        const float B30 =  c30*w0, B31 =  c31*w1, B32 = -n32*w2;

        s0 = s1 = s2 = s3 = 0.f;
        float m0 = 0.f, m1 = 0.f, m2 = 0.f, m3 = 0.f;   // this lane's dx

        // prefetch group 0's columns: g=0 -> As + 0*NV + 4*(lane ^ 0)
        const float* cb0 = As + 4*lane;
        float4 A0 = *(const float4*)(cb0 + 0*NV);
        float4 A1 = *(const float4*)(cb0 + 1*NV);
        float4 A2 = *(const float4*)(cb0 + 2*NV);
        float4 A3 = *(const float4*)(cb0 + 3*NV);

#pragma unroll 4
        for (int g = 0; g < 32; ++g) {
            // prefetch next group's columns (hidden under the chain below)
            const int gn = (g + 1) & 31;
            const float* nb = As + (4*gn)*NV + 4*(lane ^ (gn & 7));
            const float4 N0 = *(const float4*)(nb + 0*NV);
            const float4 N1 = *(const float4*)(nb + 1*NV);
            const float4 N2 = *(const float4*)(nb + 2*NV);
            const float4 N3 = *(const float4*)(nb + 3*NV);

            // candidate 4x4 solve (valid on lane g); dx0 + its shfl go first
            const float r0 = fmaf(-om, s0, F0);
            const float r1 = fmaf(-om, s1, F1);
            const float r2 = fmaf(-om, s2, F2);
            const float r3 = fmaf(-om, s3, F3);
            const float dx0 = w0*r0;
            const float e0 = __shfl_sync(0xffffffffu, dx0, g);
            const float dx1 = fmaf(B10, r0, w1*r1);
            const float e1 = __shfl_sync(0xffffffffu, dx1, g);
            const float t2  = fmaf(B21, r1, w2*r2);
            const float dx2 = fmaf(B20, r0, t2);
            const float e2 = __shfl_sync(0xffffffffu, dx2, g);
            const float ua  = fmaf(B31, r1, B30*r0);
            const float ub  = fmaf(w3,  r3, B32*r2);
            const float dx3 = ua + ub;
            const float e3 = __shfl_sync(0xffffffffu, dx3, g);

            m0 = (lane == g) ? dx0 : m0;
            m1 = (lane == g) ? dx1 : m1;
            m2 = (lane == g) ? dx2 : m2;
            m3 = (lane == g) ? dx3 : m3;

            // apply columns 4g..4g+3 to all rows; e0 consumed first
            s0 = fmaf(A3.x,e3, fmaf(A2.x,e2, fmaf(A1.x,e1, fmaf(A0.x,e0, s0))));
            s1 = fmaf(A3.y,e3, fmaf(A2.y,e2, fmaf(A1.y,e1, fmaf(A0.y,e0, s1))));
            s2 = fmaf(A3.z,e3, fmaf(A2.z,e2, fmaf(A1.z,e1, fmaf(A0.z,e0, s2))));
            s3 = fmaf(A3.w,e3, fmaf(A2.w,e2, fmaf(A1.w,e1, fmaf(A0.w,e0, s3))));

            A0 = N0; A1 = N1; A2 = N2; A3 = N3;
        }

        // x <- x - omega*dx ;  F <- F - omega*(A@dx) - x^3 + x_new^3
        const float xn0 = fmaf(-om, m0, xv.x);
        const float xn1 = fmaf(-om, m1, xv.y);
        const float xn2 = fmaf(-om, m2, xv.z);
        const float xn3 = fmaf(-om, m3, xv.w);
        F0 = fmaf(-om, s0, F0) - xv.x*xv.x*xv.x + xn0*xn0*xn0;
        F1 = fmaf(-om, s1, F1) - xv.y*xv.y*xv.y + xn1*xn1*xn1;
        F2 = fmaf(-om, s2, F2) - xv.z*xv.z*xv.z + xn2*xn2*xn2;
        F3 = fmaf(-om, s3, F3) - xv.w*xv.w*xv.w + xn3*xn3*xn3;
        xv.x = xn0; xv.y = xn1; xv.z = xn2; xv.w = xn3;
    }

    *(float4*)(Xout + (size_t)batch*NV + 4*lane) = xv;
}

extern "C" void kernel_launch(void* const* d_in, const int* in_sizes, int n_in,
                              void* d_out, int out_size)
{
    const float* x  = (const float*)d_in[0];   // (B,128)
    const float* A  = (const float*)d_in[1];   // (B,128,128)
    const float* b  = (const float*)d_in[2];   // (B,128)
    const float* om = (const float*)d_in[3];   // (B,1)

    const int B = in_sizes[1] / (NV * NV);
    const int smem = NV * NV * (int)sizeof(float);   // 64 KB

    cudaFuncSetAttribute(newton_sor_kernel,
                         cudaFuncAttributeMaxDynamicSharedMemorySize, smem);
    newton_sor_kernel<<<B, 32, smem>>>(x, A, b, om, (float*)d_out);
}

// round 4
// speedup vs baseline: 3.7032x; 1.0535x over previous
#include <cuda_runtime.h>

#define NV 128
#define NITER 16

typedef unsigned long long ull;

__device__ __forceinline__ ull splat2(float e) {
    ull r; asm("mov.b64 %0, {%1, %1};" : "=l"(r) : "f"(e)); return r;
}
__device__ __forceinline__ ull pack2(float a, float b) {
    ull r; asm("mov.b64 %0, {%1, %2};" : "=l"(r) : "f"(a), "f"(b)); return r;
}
__device__ __forceinline__ void unpack2(ull v, float& a, float& b) {
    asm("mov.b64 {%0, %1}, %2;" : "=f"(a), "=f"(b) : "l"(v));
}
__device__ __forceinline__ ull ffma2(ull a, ull b, ull c) {
    ull d; asm("fma.rn.f32x2 %0, %1, %2, %3;" : "=l"(d) : "l"(a), "l"(b), "l"(c)); return d;
}
__device__ __forceinline__ ull fadd2(ull a, ull b) {
    ull d; asm("add.rn.f32x2 %0, %1, %2;" : "=l"(d) : "l"(a), "l"(b)); return d;
}

// One warp per batch. A (128x128 fp32) lives in SMEM (XOR-chunk swizzled,
// conflict-free for transposed store and per-column LDS.128 reads).
// Lane l owns rows 4l..4l+3. Substitution for
//   M dx = F,  M = diag(A_ii+3x_i^2) + omega*strict_lower(A)
// runs in 32 groups of 4 columns, carried in the y = -omega*dx domain:
//   t   = F - omega*(partial A@dx)    (accumulated as t += A[:,c]*y_c)
//   y   = C * t   (C = -omega * inv(I+N) * W, 4x4 exact expansion, off-chain)
//   x'  = x + y
// Matvec rows are processed two-at-a-time with Blackwell packed fp32 FMA
// (fma.rn.f32x2), halving FMA-pipe issue pressure. After all 32 groups,
// t = F - omega*A@dx, so F' = t - x^3 + x'^3 exactly.
__global__ void __launch_bounds__(32, 3)
newton_sor_kernel(const float* __restrict__ Xin,
                  const float* __restrict__ A,
                  const float* __restrict__ Bv,
                  const float* __restrict__ Om,
                  float* __restrict__ Xout)
{
    extern __shared__ float As[];
    const int batch = blockIdx.x;
    const int lane  = threadIdx.x;
    const float* Ab = A + (size_t)batch * (NV * NV);

    float d0=0.f,d1=0.f,d2=0.f,d3=0.f;
    float a10=0.f,a20=0.f,a21=0.f,a30=0.f,a31=0.f,a32=0.f;

    // ---- Load A: coalesced LDG.128, 4x4 register transpose, swizzled STS.128
#pragma unroll 4
    for (int ib = 0; ib < 32; ++ib) {
        const float4 r0 = *(const float4*)(Ab + (size_t)(4*ib+0)*NV + 4*lane);
        const float4 r1 = *(const float4*)(Ab + (size_t)(4*ib+1)*NV + 4*lane);
        const float4 r2 = *(const float4*)(Ab + (size_t)(4*ib+2)*NV + 4*lane);
        const float4 r3 = *(const float4*)(Ab + (size_t)(4*ib+3)*NV + 4*lane);
        if (lane == ib) {
            d0 = r0.x; d1 = r1.y; d2 = r2.z; d3 = r3.w;
            a10 = r1.x;
            a20 = r2.x; a21 = r2.y;
            a30 = r3.x; a31 = r3.y; a32 = r3.z;
        }
        float* base = As + (4*lane)*NV + 4*(ib ^ (lane & 7));
        *(float4*)(base + 0*NV) = make_float4(r0.x, r1.x, r2.x, r3.x);
        *(float4*)(base + 1*NV) = make_float4(r0.y, r1.y, r2.y, r3.y);
        *(float4*)(base + 2*NV) = make_float4(r0.z, r1.z, r2.z, r3.z);
        *(float4*)(base + 3*NV) = make_float4(r0.w, r1.w, r2.w, r3.w);
    }
    __syncwarp();

    float4 xv = *(const float4*)(Xin + (size_t)batch*NV + 4*lane);
    const float4 bv = *(const float4*)(Bv + (size_t)batch*NV + 4*lane);
    const float om = Om[batch];

    // ---- Initial residual: t = A@x (packed), then F = t + x^3 - b
    ull t01 = 0ull, t23 = 0ull;
#pragma unroll 4
    for (int g = 0; g < 32; ++g) {
        const ull e00 = splat2(__shfl_sync(0xffffffffu, xv.x, g));
        const ull e11 = splat2(__shfl_sync(0xffffffffu, xv.y, g));
        const ull e22 = splat2(__shfl_sync(0xffffffffu, xv.z, g));
        const ull e33 = splat2(__shfl_sync(0xffffffffu, xv.w, g));
        const char* cb = (const char*)(As + (4*g)*NV + 4*(lane ^ (g & 7)));
        const ulonglong2 A0 = *(const ulonglong2*)(cb + 0*NV*4);
        const ulonglong2 A1 = *(const ulonglong2*)(cb + 1*NV*4);
        const ulonglong2 A2 = *(const ulonglong2*)(cb + 2*NV*4);
        const ulonglong2 A3 = *(const ulonglong2*)(cb + 3*NV*4);
        t01 = ffma2(A3.x, e33, ffma2(A2.x, e22, ffma2(A1.x, e11, ffma2(A0.x, e00, t01))));
        t23 = ffma2(A3.y, e33, ffma2(A2.y, e22, ffma2(A1.y, e11, ffma2(A0.y, e00, t23))));
    }
    t01 = fadd2(t01, pack2(xv.x*xv.x*xv.x - bv.x, xv.y*xv.y*xv.y - bv.y));
    t23 = fadd2(t23, pack2(xv.z*xv.z*xv.z - bv.z, xv.w*xv.w*xv.w - bv.w));
    // t01/t23 now hold F; each iteration consumes them as the running t.

    // ---- Newton-SOR iterations (fixed count; extra post-convergence
    //      iterations cannot move x by more than tol)
#pragma unroll 1
    for (int it = 0; it < NITER; ++it) {
        // Solve coefficients, all OFF the critical path.
        const float w0 = __fdividef(1.0f, fmaf(3.0f*xv.x, xv.x, d0));
        const float w1 = __fdividef(1.0f, fmaf(3.0f*xv.y, xv.y, d1));
        const float w2 = __fdividef(1.0f, fmaf(3.0f*xv.z, xv.z, d2));
        const float w3 = __fdividef(1.0f, fmaf(3.0f*xv.w, xv.w, d3));
        // N = om*W*L; (I+N)^{-1} = I - N + N^2 - N^3 (exact, strictly lower N)
        const float n10 = om*w1*a10;
        const float n20 = om*w2*a20, n21 = om*w2*a21;
        const float n30 = om*w3*a30, n31 = om*w3*a31, n32 = om*w3*a32;
        const float c20 = fmaf(n21, n10, -n20);
        const float c31 = fmaf(n32, n21, -n31);
        const float t30 = fmaf(-n32, n21, n31);
        const float c30 = fmaf(t30, n10, fmaf(n32, n20, -n30));
        // y = C*t with C = -om * Bm  (Bm: diag w, lower B__)
        const float q0 = -om*w0, q1 = -om*w1, q2 = -om*w2, q3 = -om*w3;
        const float C10 =  om*n10*w0;
        const float C20 = -om*c20*w0, C21 =  om*n21*w1;
        const float C30 = -om*c30*w0, C31 = -om*c31*w1, C32 =  om*n32*w2;

        float m0 = 0.f, m1 = 0.f, m2 = 0.f, m3 = 0.f;   // this lane's y

        // prefetch group 0's columns: As + 0*NV + 4*(lane ^ 0)
        const char* cb0 = (const char*)(As + 4*lane);
        ulonglong2 A0 = *(const ulonglong2*)(cb0 + 0*NV*4);
        ulonglong2 A1 = *(const ulonglong2*)(cb0 + 1*NV*4);
        ulonglong2 A2 = *(const ulonglong2*)(cb0 + 2*NV*4);
        ulonglong2 A3 = *(const ulonglong2*)(cb0 + 3*NV*4);

#pragma unroll 4
        for (int g = 0; g < 32; ++g) {
            const int gn = (g + 1) & 31;
            const char* nb = (const char*)(As + (4*gn)*NV + 4*(lane ^ (gn & 7)));
            const ulonglong2 N0 = *(const ulonglong2*)(nb + 0*NV*4);
            const ulonglong2 N1 = *(const ulonglong2*)(nb + 1*NV*4);
            const ulonglong2 N2 = *(const ulonglong2*)(nb + 2*NV*4);
            const ulonglong2 N3 = *(const ulonglong2*)(nb + 3*NV*4);

            // candidate y = C*t for this lane's rows (valid on lane g)
            float t0, t1, t2, t3;
            unpack2(t01, t0, t1);
            unpack2(t23, t2, t3);
            const float y0 = q0*t0;
            const float e0 = __shfl_sync(0xffffffffu, y0, g);
            const ull  e00 = splat2(e0);
            const float y1 = fmaf(C10, t0, q1*t1);
            const float e1 = __shfl_sync(0xffffffffu, y1, g);
            const ull  e11 = splat2(e1);
            const float u2 = fmaf(C21, t1, q2*t2);
            const float y2 = fmaf(C20, t0, u2);
            const float e2 = __shfl_sync(0xffffffffu, y2, g);
            const ull  e22 = splat2(e2);
            const float ua = fmaf(C31, t1, C30*t0);
            const float ub = fmaf(q3, t3, C32*t2);
            const float y3 = ua + ub;
            const float e3 = __shfl_sync(0xffffffffu, y3, g);
            const ull  e33 = splat2(e3);

            m0 = (lane == g) ? y0 : m0;
            m1 = (lane == g) ? y1 : m1;
            m2 = (lane == g) ? y2 : m2;
            m3 = (lane == g) ? y3 : m3;

            // t += A[:,4g..4g+3] * y  (packed, rows two-at-a-time; e0 first)
            t01 = ffma2(A3.x, e33, ffma2(A2.x, e22, ffma2(A1.x, e11, ffma2(A0.x, e00, t01))));
            t23 = ffma2(A3.y, e33, ffma2(A2.y, e22, ffma2(A1.y, e11, ffma2(A0.y, e00, t23))));

            A0 = N0; A1 = N1; A2 = N2; A3 = N3;
        }

        // x' = x + y ; F' = t - x^3 + x'^3  (t already = F - om*A@dx)
        const float xn0 = xv.x + m0;
        const float xn1 = xv.y + m1;
        const float xn2 = xv.z + m2;
        const float xn3 = xv.w + m3;
        t01 = fadd2(t01, pack2(xn0*xn0*xn0 - xv.x*xv.x*xv.x,
                               xn1*xn1*xn1 - xv.y*xv.y*xv.y));
        t23 = fadd2(t23, pack2(xn2*xn2*xn2 - xv.z*xv.z*xv.z,
                               xn3*xn3*xn3 - xv.w*xv.w*xv.w));
        xv.x = xn0; xv.y = xn1; xv.z = xn2; xv.w = xn3;
    }

    *(float4*)(Xout + (size_t)batch*NV + 4*lane) = xv;
}

extern "C" void kernel_launch(void* const* d_in, const int* in_sizes, int n_in,
                              void* d_out, int out_size)
{
    const float* x  = (const float*)d_in[0];   // (B,128)
    const float* A  = (const float*)d_in[1];   // (B,128,128)
    const float* b  = (const float*)d_in[2];   // (B,128)
    const float* om = (const float*)d_in[3];   // (B,1)

    const int B = in_sizes[1] / (NV * NV);
    const int smem = NV * NV * (int)sizeof(float);   // 64 KB

    cudaFuncSetAttribute(newton_sor_kernel,
                         cudaFuncAttributeMaxDynamicSharedMemorySize, smem);
    newton_sor_kernel<<<B, 32, smem>>>(x, A, b, om, (float*)d_out);
}